// round 1
// baseline (speedup 1.0000x reference)
#include <cuda_runtime.h>

// ---------------------------------------------------------------------------
// QuantumSentenceTransformer fused kernel.
//
// out[b,:] = ( Z( U(tanh(X[b]@W_pre + b_pre)*pi/2, q_params) ) ) @ W_post + b_post
//
// One thread per row. X staged through shared memory in coalesced
// 128-row x 32-col tiles; all small parameters in __constant__ memory
// (uniform access -> LDCU, no smem crossbar traffic). 16-dim statevector
// lives entirely in registers; CNOTs compile to register renames.
// ---------------------------------------------------------------------------

#define DCOLS   512
#define BROWS   128           // rows per block (== threads per block)
#define CH      32            // columns per smem chunk
#define NCHUNK  (DCOLS / CH)  // 16
#define PITCH   36            // smem row pitch in floats (32 + 4 pad, 4*odd -> conflict-free)

__constant__ float cW[DCOLS * 4];   // W_pre, row-major [d][q]  (8 KB)
__constant__ float cBpre[4];
__constant__ float cQ[24];          // q_params
__constant__ float cWpost[8];       // [w][j], 4x2
__constant__ float cBpost[2];

__device__ __forceinline__ float fast_tanh(float x) {
    // tanh(x) = 1 - 2/(exp(2x)+1); exact saturation at +/-inf, rel err ~1e-6
    float t = __expf(2.0f * x);
    return 1.0f - __fdividef(2.0f, t + 1.0f);
}

// RY on index-bit b (bit b = N_QUBITS-1-wire). Fully unrolled; constant b.
__device__ __forceinline__ void ry_gate(float* s, float c, float sn, int b) {
#pragma unroll
    for (int i = 0; i < 16; ++i) {
        if (!((i >> b) & 1)) {
            int j = i | (1 << b);
            float a0 = s[i], a1 = s[j];
            s[i] = fmaf(c, a0, -sn * a1);
            s[j] = fmaf(sn, a0,  c * a1);
        }
    }
}

// CNOT with control bit cb, target bit tb: pure register swap (free in SASS).
__device__ __forceinline__ void cnot_gate(float* s, int cb, int tb) {
#pragma unroll
    for (int i = 0; i < 16; ++i) {
        if (((i >> cb) & 1) && !((i >> tb) & 1)) {
            int j = i | (1 << tb);
            float t = s[i]; s[i] = s[j]; s[j] = t;
        }
    }
}

__global__ __launch_bounds__(BROWS)
void qst_kernel(const float* __restrict__ X, float* __restrict__ out)
{
    __shared__ __align__(16) float sX[BROWS * PITCH];

    const int tid = threadIdx.x;
    const long rowBase = (long)blockIdx.x * BROWS;

    const float4* __restrict__ Xv  = reinterpret_cast<const float4*>(X);
    const float4* __restrict__ cW4 = reinterpret_cast<const float4*>(cW);

    float acc0 = 0.f, acc1 = 0.f, acc2 = 0.f, acc3 = 0.f;

    // -------- matvec: pre = X[row] @ W_pre -------------------------------
    for (int ch = 0; ch < NCHUNK; ++ch) {
        __syncthreads();   // previous chunk fully consumed
#pragma unroll
        for (int j = 0; j < 8; ++j) {
            int idx = tid + BROWS * j;        // 0..1023
            int r   = idx >> 3;               // 0..127
            int c4  = idx & 7;                // 0..7
            float4 v = Xv[(rowBase + r) * (DCOLS / 4) + ch * 8 + c4];
            *reinterpret_cast<float4*>(&sX[r * PITCH + c4 * 4]) = v;
        }
        __syncthreads();

#pragma unroll
        for (int c4 = 0; c4 < 8; ++c4) {
            float4 x = *reinterpret_cast<const float4*>(&sX[tid * PITCH + c4 * 4]);
            int d = ch * CH + c4 * 4;         // uniform across warp -> LDCU
            float4 w0 = cW4[d + 0];
            float4 w1 = cW4[d + 1];
            float4 w2 = cW4[d + 2];
            float4 w3 = cW4[d + 3];
            acc0 = fmaf(x.x, w0.x, acc0); acc1 = fmaf(x.x, w0.y, acc1);
            acc2 = fmaf(x.x, w0.z, acc2); acc3 = fmaf(x.x, w0.w, acc3);
            acc0 = fmaf(x.y, w1.x, acc0); acc1 = fmaf(x.y, w1.y, acc1);
            acc2 = fmaf(x.y, w1.z, acc2); acc3 = fmaf(x.y, w1.w, acc3);
            acc0 = fmaf(x.z, w2.x, acc0); acc1 = fmaf(x.z, w2.y, acc1);
            acc2 = fmaf(x.z, w2.z, acc2); acc3 = fmaf(x.z, w2.w, acc3);
            acc0 = fmaf(x.w, w3.x, acc0); acc1 = fmaf(x.w, w3.y, acc1);
            acc2 = fmaf(x.w, w3.z, acc2); acc3 = fmaf(x.w, w3.w, acc3);
        }
    }

    // -------- encoder angles --------------------------------------------
    const float PI4 = 0.7853981633974483f;   // pi/4 (half of pi/2 scale)
    float h0 = fast_tanh(acc0 + cBpre[0]) * PI4;
    float h1 = fast_tanh(acc1 + cBpre[1]) * PI4;
    float h2 = fast_tanh(acc2 + cBpre[2]) * PI4;
    float h3 = fast_tanh(acc3 + cBpre[3]) * PI4;

    // -------- quantum circuit (16-dim statevector in registers) ----------
    float s[16];
#pragma unroll
    for (int i = 0; i < 16; ++i) s[i] = 0.25f;

    ry_gate(s, __cosf(h0), __sinf(h0), 3);   // wire 0 -> bit 3
    ry_gate(s, __cosf(h1), __sinf(h1), 2);
    ry_gate(s, __cosf(h2), __sinf(h2), 1);
    ry_gate(s, __cosf(h3), __sinf(h3), 0);

#pragma unroll
    for (int k = 0; k < 6; ++k) {
        cnot_gate(s, 3, 2);   // CNOT(0,1)
        cnot_gate(s, 1, 0);   // CNOT(2,3)
        cnot_gate(s, 2, 1);   // CNOT(1,2)
        { float h = cQ[4*k + 0] * 0.5f; ry_gate(s, __cosf(h), __sinf(h), 3); }
        { float h = cQ[4*k + 1] * 0.5f; ry_gate(s, __cosf(h), __sinf(h), 2); }
        { float h = cQ[4*k + 2] * 0.5f; ry_gate(s, __cosf(h), __sinf(h), 1); }
        { float h = cQ[4*k + 3] * 0.5f; ry_gate(s, __cosf(h), __sinf(h), 0); }
    }

    // -------- expectation values <Z_w> -----------------------------------
    float e0 = 0.f, e1 = 0.f, e2 = 0.f, e3 = 0.f;
#pragma unroll
    for (int i = 0; i < 16; ++i) {
        float p = s[i] * s[i];
        e0 += ((i >> 3) & 1) ? -p : p;
        e1 += ((i >> 2) & 1) ? -p : p;
        e2 += ((i >> 1) & 1) ? -p : p;
        e3 += ( i       & 1) ? -p : p;
    }

    // -------- post head ---------------------------------------------------
    float o0 = cBpost[0];
    float o1 = cBpost[1];
    o0 = fmaf(e0, cWpost[0], o0); o1 = fmaf(e0, cWpost[1], o1);
    o0 = fmaf(e1, cWpost[2], o0); o1 = fmaf(e1, cWpost[3], o1);
    o0 = fmaf(e2, cWpost[4], o0); o1 = fmaf(e2, cWpost[5], o1);
    o0 = fmaf(e3, cWpost[6], o0); o1 = fmaf(e3, cWpost[7], o1);

    float2* out2 = reinterpret_cast<float2*>(out);
    out2[rowBase + tid] = make_float2(o0, o1);
}

extern "C" void kernel_launch(void* const* d_in, const int* in_sizes, int n_in,
                              void* d_out, int out_size)
{
    const float* X = (const float*)d_in[0];

    // Small parameters -> constant memory (D2D async copies: graph-capturable,
    // allocation-free).
    cudaMemcpyToSymbolAsync(cW,     d_in[1], DCOLS * 4 * sizeof(float), 0,
                            cudaMemcpyDeviceToDevice, 0);
    cudaMemcpyToSymbolAsync(cBpre,  d_in[2], 4  * sizeof(float), 0,
                            cudaMemcpyDeviceToDevice, 0);
    cudaMemcpyToSymbolAsync(cQ,     d_in[3], 24 * sizeof(float), 0,
                            cudaMemcpyDeviceToDevice, 0);
    cudaMemcpyToSymbolAsync(cWpost, d_in[4], 8  * sizeof(float), 0,
                            cudaMemcpyDeviceToDevice, 0);
    cudaMemcpyToSymbolAsync(cBpost, d_in[5], 2  * sizeof(float), 0,
                            cudaMemcpyDeviceToDevice, 0);

    int B = in_sizes[0] / DCOLS;          // 131072
    qst_kernel<<<B / BROWS, BROWS, 0, 0>>>(X, (float*)d_out);
}

// round 2
// speedup vs baseline: 1.0992x; 1.0992x over previous
#include <cuda_runtime.h>

// ---------------------------------------------------------------------------
// QuantumSentenceTransformer fused kernel, round 2.
//
// One thread per row. X streamed via cp.async (LDGSTS) through a 3-stage
// shared-memory pipeline (8KB/stage, XOR-swizzled: conflict-free stores AND
// loads with zero padding). W_pre in __constant__ (LDCU uniform port).
// Matvec uses packed fma.rn.f32x2. 16-dim statevector in registers.
// ---------------------------------------------------------------------------

#define DCOLS   512
#define BROWS   128            // rows per block == threads per block
#define CH      16             // columns per pipeline stage
#define NCHUNK  (DCOLS / CH)   // 32
#define STAGES  3
#define STAGE_F (BROWS * CH)   // 2048 floats = 8KB per stage

__constant__ float cW[DCOLS * 4];   // W_pre row-major [d][q], 8KB

// ---- f32x2 packed math helpers --------------------------------------------
__device__ __forceinline__ unsigned long long ffma2(
    unsigned long long a, unsigned long long b, unsigned long long c) {
    unsigned long long d;
    asm("fma.rn.f32x2 %0, %1, %2, %3;" : "=l"(d) : "l"(a), "l"(b), "l"(c));
    return d;
}
__device__ __forceinline__ unsigned long long pack2(float x) {
    unsigned long long p;
    unsigned int u = __float_as_uint(x);
    asm("mov.b64 %0, {%1, %1};" : "=l"(p) : "r"(u));
    return p;
}
__device__ __forceinline__ void unpack2(unsigned long long p, float& lo, float& hi) {
    asm("mov.b64 {%0, %1}, %2;" : "=f"(lo), "=f"(hi) : "l"(p));
}

// ---- cp.async helpers ------------------------------------------------------
__device__ __forceinline__ void cp_async16(unsigned int dst, const void* src) {
    asm volatile("cp.async.cg.shared.global [%0], [%1], 16;"
                 :: "r"(dst), "l"(src));
}
__device__ __forceinline__ void cp_commit() {
    asm volatile("cp.async.commit_group;");
}
__device__ __forceinline__ void cp_wait1() {
    asm volatile("cp.async.wait_group 1;");
}
__device__ __forceinline__ void cp_wait0() {
    asm volatile("cp.async.wait_group 0;");
}

__device__ __forceinline__ float fast_tanh(float x) {
    float t = __expf(2.0f * x);
    return 1.0f - __fdividef(2.0f, t + 1.0f);
}

// RY on index-bit b. Fully unrolled; constant b.
__device__ __forceinline__ void ry_gate(float* s, float c, float sn, int b) {
#pragma unroll
    for (int i = 0; i < 16; ++i) {
        if (!((i >> b) & 1)) {
            int j = i | (1 << b);
            float a0 = s[i], a1 = s[j];
            s[i] = fmaf(c, a0, -sn * a1);
            s[j] = fmaf(sn, a0,  c * a1);
        }
    }
}
// CNOT: pure register rename.
__device__ __forceinline__ void cnot_gate(float* s, int cb, int tb) {
#pragma unroll
    for (int i = 0; i < 16; ++i) {
        if (((i >> cb) & 1) && !((i >> tb) & 1)) {
            int j = i | (1 << tb);
            float t = s[i]; s[i] = s[j]; s[j] = t;
        }
    }
}

__global__ __launch_bounds__(BROWS, 8)
void qst_kernel(const float* __restrict__ X,
                const float* __restrict__ bpre,
                const float* __restrict__ qp,
                const float* __restrict__ wpost,
                const float* __restrict__ bpost,
                float* __restrict__ out)
{
    __shared__ __align__(16) float sX[STAGES * STAGE_F];   // 24KB

    const int tid = threadIdx.x;
    const long rowBase = (long)blockIdx.x * BROWS;

    // ---- loader mapping: 4 x cp.async per thread per stage -------------
    // idx = tid + 128*j ; r = idx>>2 ; c4 = idx&3
    // gmem src : row r, float4 #c4 of the 4-float4 chunk
    // smem dst : float4 slot r*4 + (c4 ^ swz(r)) ; swz(r) = (r + (r>>2)) & 3
    const char* gsrc[4];
    unsigned int sdst[4];
    unsigned int sbase = (unsigned int)__cvta_generic_to_shared(sX);
#pragma unroll
    for (int j = 0; j < 4; ++j) {
        int idx = tid + BROWS * j;
        int r   = idx >> 2;
        int c4  = idx & 3;
        gsrc[j] = (const char*)(X + (rowBase + r) * DCOLS + c4 * 4);
        int slot = r * 4 + (c4 ^ ((r + (r >> 2)) & 3));
        sdst[j] = sbase + (unsigned int)slot * 16u;
    }

    // swizzle for this thread's compute reads
    const int sw = (tid + (tid >> 2)) & 3;
    const float4* const srowBase = reinterpret_cast<const float4*>(sX) + tid * 4;
    const ulonglong2* const cW2  = reinterpret_cast<const ulonglong2*>(cW);

    unsigned long long acc01 = 0ull, acc23 = 0ull;

    // ---- prologue: issue stage 0 ----------------------------------------
#pragma unroll
    for (int j = 0; j < 4; ++j) cp_async16(sdst[j], gsrc[j]);
    cp_commit();

    // ---- pipelined matvec ------------------------------------------------
#pragma unroll 1
    for (int ch = 0; ch < NCHUNK; ++ch) {
        if (ch + 1 < NCHUNK) {
            unsigned int soff = (unsigned int)(((ch + 1) % STAGES) * STAGE_F * 4);
            const long goff = (long)(ch + 1) * (CH * 4);
#pragma unroll
            for (int j = 0; j < 4; ++j) cp_async16(sdst[j] + soff, gsrc[j] + goff);
            cp_commit();
            cp_wait1();            // stage ch has landed
        } else {
            cp_wait0();
        }
        __syncthreads();

        const float4* srow = srowBase + (ch % STAGES) * (STAGE_F / 4);
#pragma unroll
        for (int c4 = 0; c4 < 4; ++c4) {
            float4 x = srow[c4 ^ sw];
            float xs[4] = {x.x, x.y, x.z, x.w};
            int d = ch * CH + c4 * 4;
#pragma unroll
            for (int k = 0; k < 4; ++k) {
                ulonglong2 w = cW2[d + k];          // (W[d][0],W[d][1]) , (W[d][2],W[d][3])
                unsigned long long xp = pack2(xs[k]);
                acc01 = ffma2(xp, w.x, acc01);
                acc23 = ffma2(xp, w.y, acc23);
            }
        }
    }

    float acc0, acc1, acc2, acc3;
    unpack2(acc01, acc0, acc1);
    unpack2(acc23, acc2, acc3);

    // ---- encoder angles --------------------------------------------------
    const float PI4 = 0.7853981633974483f;
    float h0 = fast_tanh(acc0 + __ldg(bpre + 0)) * PI4;
    float h1 = fast_tanh(acc1 + __ldg(bpre + 1)) * PI4;
    float h2 = fast_tanh(acc2 + __ldg(bpre + 2)) * PI4;
    float h3 = fast_tanh(acc3 + __ldg(bpre + 3)) * PI4;

    // ---- quantum circuit -------------------------------------------------
    float s[16];
#pragma unroll
    for (int i = 0; i < 16; ++i) s[i] = 0.25f;

    ry_gate(s, __cosf(h0), __sinf(h0), 3);
    ry_gate(s, __cosf(h1), __sinf(h1), 2);
    ry_gate(s, __cosf(h2), __sinf(h2), 1);
    ry_gate(s, __cosf(h3), __sinf(h3), 0);

#pragma unroll
    for (int k = 0; k < 6; ++k) {
        cnot_gate(s, 3, 2);
        cnot_gate(s, 1, 0);
        cnot_gate(s, 2, 1);
        { float h = __ldg(qp + 4*k + 0) * 0.5f; ry_gate(s, __cosf(h), __sinf(h), 3); }
        { float h = __ldg(qp + 4*k + 1) * 0.5f; ry_gate(s, __cosf(h), __sinf(h), 2); }
        { float h = __ldg(qp + 4*k + 2) * 0.5f; ry_gate(s, __cosf(h), __sinf(h), 1); }
        { float h = __ldg(qp + 4*k + 3) * 0.5f; ry_gate(s, __cosf(h), __sinf(h), 0); }
    }

    // ---- <Z_w> expectation values ---------------------------------------
    float e0 = 0.f, e1 = 0.f, e2 = 0.f, e3 = 0.f;
#pragma unroll
    for (int i = 0; i < 16; ++i) {
        float p = s[i] * s[i];
        e0 += ((i >> 3) & 1) ? -p : p;
        e1 += ((i >> 2) & 1) ? -p : p;
        e2 += ((i >> 1) & 1) ? -p : p;
        e3 += ( i       & 1) ? -p : p;
    }

    // ---- post head -------------------------------------------------------
    float o0 = __ldg(bpost + 0);
    float o1 = __ldg(bpost + 1);
    o0 = fmaf(e0, __ldg(wpost + 0), o0); o1 = fmaf(e0, __ldg(wpost + 1), o1);
    o0 = fmaf(e1, __ldg(wpost + 2), o0); o1 = fmaf(e1, __ldg(wpost + 3), o1);
    o0 = fmaf(e2, __ldg(wpost + 4), o0); o1 = fmaf(e2, __ldg(wpost + 5), o1);
    o0 = fmaf(e3, __ldg(wpost + 6), o0); o1 = fmaf(e3, __ldg(wpost + 7), o1);

    reinterpret_cast<float2*>(out)[rowBase + tid] = make_float2(o0, o1);
}

extern "C" void kernel_launch(void* const* d_in, const int* in_sizes, int n_in,
                              void* d_out, int out_size)
{
    const float* X     = (const float*)d_in[0];
    const float* bpre  = (const float*)d_in[2];
    const float* qp    = (const float*)d_in[3];
    const float* wpost = (const float*)d_in[4];
    const float* bpost = (const float*)d_in[5];

    // Only W_pre goes to constant memory (hot, needs the LDCU uniform port).
    cudaMemcpyToSymbolAsync(cW, d_in[1], DCOLS * 4 * sizeof(float), 0,
                            cudaMemcpyDeviceToDevice, 0);

    int B = in_sizes[0] / DCOLS;          // 131072
    qst_kernel<<<B / BROWS, BROWS, 0, 0>>>(X, bpre, qp, wpost, bpost,
                                           (float*)d_out);
}